// round 6
// baseline (speedup 1.0000x reference)
#include <cuda_runtime.h>

// CRF NLL, exp-domain forward scan, f32x2 FMAs, deep prefetch.
// TWO chains (batches b and b+256) interleaved per 64-thread block:
// one barrier per step serves both chains; the two 32-FMA2 dot products
// are independent -> double ILP in the latency-bound step.
// q_s[to] = (sum_from q_{s-1}[from] * E[from,to]) * exp(f_s[to]) / q_{s-1}[0]
// C_s = C_{s-1} + log(q_{s-1}[0]);  part_s = log(q_s) + C_s.

constexpr int Bb = 512;
constexpr int Ss = 512;
constexpr int Tt = 64;
constexpr int START = Tt - 2;
constexpr int STOP  = Tt - 1;
constexpr int PD    = 4;       // feats prefetch depth (steps)
constexpr int NBLK  = Bb / 2;  // 256 blocks, 2 chains each

__device__ float g_partial[Bb];
__device__ unsigned int g_count = 0;

typedef unsigned long long u64;

static __device__ __forceinline__ u64 fma2(u64 a, u64 b, u64 c) {
    u64 d;
    asm("fma.rn.f32x2 %0, %1, %2, %3;" : "=l"(d) : "l"(a), "l"(b), "l"(c));
    return d;
}
static __device__ __forceinline__ u64 add2(u64 a, u64 b) {
    u64 d;
    asm("add.rn.f32x2 %0, %1, %2;" : "=l"(d) : "l"(a), "l"(b));
    return d;
}
static __device__ __forceinline__ u64 pack2(float lo, float hi) {
    u64 d;
    asm("mov.b64 %0, {%1, %2};" : "=l"(d) : "f"(lo), "f"(hi));
    return d;
}
static __device__ __forceinline__ void unpack2(u64 v, float& lo, float& hi) {
    asm("mov.b64 {%0, %1}, %2;" : "=f"(lo), "=f"(hi) : "l"(v));
}
static __device__ __forceinline__ float rcp_approx(float x) {
    float r;
    asm("rcp.approx.f32 %0, %1;" : "=f"(r) : "f"(x));
    return r;
}

__global__ __launch_bounds__(Tt) void crf_kernel(
    const float* __restrict__ feats,
    const unsigned char* __restrict__ mask8,
    const int* __restrict__ tags,
    const float* __restrict__ trans,
    float* __restrict__ out)
{
    const int bA = blockIdx.x;
    const int bB = blockIdx.x + NBLK;
    const int to = threadIdx.x;   // 0..63

    __shared__ ulonglong2 qA[2][16];   // chain A q (exp domain), double-buffered
    __shared__ ulonglong2 qB[2][16];   // chain B
    __shared__ float red[Tt];
    __shared__ int   ired[Tt];
    __shared__ int   shLA, shLB;
    __shared__ bool  is_last;

    // ---- mask layout probe (uint8 vs int32) + sequence lengths ----
    const int* mask32 = reinterpret_cast<const int*>(mask8);
    const bool is32 = (mask8[0] == 1 && mask8[1] == 0 && mask8[2] == 0 && mask8[3] == 0);

    int cA = 0, cB = 0;
    #pragma unroll
    for (int k = 0; k < Ss / Tt; ++k) {
        int s = to + k * Tt;
        int va = is32 ? mask32[bA * Ss + s] : (int)mask8[bA * Ss + s];
        int vb = is32 ? mask32[bB * Ss + s] : (int)mask8[bB * Ss + s];
        cA += (va != 0);
        cB += (vb != 0);
    }
    ired[to] = cA | (cB << 16);
    __syncthreads();
    if (to == 0) {
        int la = 0, lb = 0;
        #pragma unroll
        for (int i = 0; i < Tt; ++i) { la += ired[i] & 0xffff; lb += ired[i] >> 16; }
        shLA = la; shLB = lb;
    }
    __syncthreads();
    const int La = shLA, Lb = shLB;   // each >= S/2 = 256
    const int minL = (La < Lb) ? La : Lb;
    const int maxL = (La > Lb) ? La : Lb;

    const float* fA = feats + (size_t)bA * Ss * Tt;
    const float* fB = feats + (size_t)bB * Ss * Tt;
    const int*   tA = tags + bA * Ss;
    const int*   tB = tags + bB * Ss;

    // ---- gold path scores ----
    float ga = 0.f, gb = 0.f;
    for (int s = to; s < La; s += Tt) {
        int t1 = tA[s];
        int t0 = (s == 0) ? START : tA[s - 1];
        ga += fA[s * Tt + t1] + trans[t0 * Tt + t1];
    }
    for (int s = to; s < Lb; s += Tt) {
        int t1 = tB[s];
        int t0 = (s == 0) ? START : tB[s - 1];
        gb += fB[s * Tt + t1] + trans[t0 * Tt + t1];
    }
    red[to] = ga;
    __syncthreads();
    float goldA = 0.f, goldB = 0.f;   // valid in to==0 only
    if (to == 0) {
        #pragma unroll
        for (int i = 0; i < Tt; ++i) goldA += red[i];
        goldA += trans[tA[La - 1] * Tt + STOP];
    }
    __syncthreads();
    red[to] = gb;
    __syncthreads();
    if (to == 0) {
        #pragma unroll
        for (int i = 0; i < Tt; ++i) goldB += red[i];
        goldB += trans[tB[Lb - 1] * Tt + STOP];
    }

    // ---- E pairs (shared by both chains): E2[k] = (e^tr[2k][to], e^tr[2k+1][to]) ----
    u64 E2[Tt / 2];
    #pragma unroll
    for (int k = 0; k < Tt / 2; ++k) {
        E2[k] = pack2(__expf(trans[(2 * k) * Tt + to]),
                      __expf(trans[(2 * k + 1) * Tt + to]));
    }

    // ---- init both chains ----
    const float tS = trans[START * Tt + to];
    const float tS0 = trans[START * Tt];
    const float cA0 = fA[0] + tS0;
    const float cB0 = fB[0] + tS0;
    float logCa = cA0, logCb = cB0;
    reinterpret_cast<float*>(qA[0])[to] = __expf(fA[to] + tS - cA0);
    reinterpret_cast<float*>(qB[0])[to] = __expf(fB[to] + tS - cB0);
    __syncthreads();

    // ---- feats pipelines (exp at prefetch time, off critical path) ----
    float efA[PD], efB[PD];
    #pragma unroll
    for (int r = 0; r < PD; ++r) {
        efA[r] = __expf(fA[(1 + r) * Tt + to]);
        efB[r] = __expf(fB[(1 + r) * Tt + to]);
    }

    float curA = 0.f, curB = 0.f;

    // one chain-step (no internal sync)
    auto chain = [&](const ulonglong2* qp, float* qw, float e,
                     float& logC, float& cur) {
        ulonglong2 w = qp[0];
        float q0, qd;
        unpack2(w.x, q0, qd);
        const float rc = rcp_approx(q0);    // overlaps FMA block
        logC += __logf(q0);                 // independent side chain

        u64 a0 = fma2(w.x, E2[0], 0ull);
        u64 a1 = fma2(w.y, E2[1], 0ull);
        u64 a2 = 0ull, a3 = 0ull;
        #pragma unroll
        for (int j = 1; j < 16; ++j) {
            w = qp[j];
            if (j & 1) { a2 = fma2(w.x, E2[2 * j], a2); a3 = fma2(w.y, E2[2 * j + 1], a3); }
            else       { a0 = fma2(w.x, E2[2 * j], a0); a1 = fma2(w.y, E2[2 * j + 1], a1); }
        }
        float lo, hi;
        unpack2(add2(add2(a0, a2), add2(a1, a3)), lo, hi);
        cur = (lo + hi) * (e * rc);
        qw[to] = cur;
    };

    // ---- fused scan: both chains share one barrier per step ----
    int s = 1;
    for (; s + (PD - 1) < minL; ) {
        #pragma unroll
        for (int r = 0; r < PD; ++r) {
            const float ea = efA[r], eb = efB[r];
            if (s + PD < La) efA[r] = __expf(fA[(s + PD) * Tt + to]);
            if (s + PD < Lb) efB[r] = __expf(fB[(s + PD) * Tt + to]);
            __syncthreads();
            chain(qA[(s - 1) & 1], reinterpret_cast<float*>(qA[s & 1]), ea, logCa, curA);
            chain(qB[(s - 1) & 1], reinterpret_cast<float*>(qB[s & 1]), eb, logCb, curB);
            ++s;
        }
    }
    // to minL (dynamic ring index, <= PD-1 iters)
    for (; s < minL; ++s) {
        int r = (s - 1) & (PD - 1);
        const float ea = efA[r], eb = efB[r];
        if (s + PD < La) efA[r] = __expf(fA[(s + PD) * Tt + to]);
        if (s + PD < Lb) efB[r] = __expf(fB[(s + PD) * Tt + to]);
        __syncthreads();
        chain(qA[(s - 1) & 1], reinterpret_cast<float*>(qA[s & 1]), ea, logCa, curA);
        chain(qB[(s - 1) & 1], reinterpret_cast<float*>(qB[s & 1]), eb, logCb, curB);
    }
    // tail: only the longer chain remains
    for (; s < maxL; ++s) {
        int r = (s - 1) & (PD - 1);
        const bool aAct = s < La;
        const float e = aAct ? efA[r] : efB[r];
        if (aAct) { if (s + PD < La) efA[r] = __expf(fA[(s + PD) * Tt + to]); }
        else      { if (s + PD < Lb) efB[r] = __expf(fB[(s + PD) * Tt + to]); }
        __syncthreads();
        if (aAct) chain(qA[(s - 1) & 1], reinterpret_cast<float*>(qA[s & 1]), e, logCa, curA);
        else      chain(qB[(s - 1) & 1], reinterpret_cast<float*>(qB[s & 1]), e, logCb, curB);
    }

    // ---- final transition to STOP, both chains ----
    const float eStop = __expf(trans[to * Tt + STOP]);
    red[to] = curA * eStop;
    __syncthreads();
    if (to == 0) {
        float tot = 0.f;
        #pragma unroll
        for (int i = 0; i < Tt; ++i) tot += red[i];
        g_partial[bA] = (logCa + __logf(tot)) - goldA;
    }
    __syncthreads();
    red[to] = curB * eStop;
    __syncthreads();
    if (to == 0) {
        float tot = 0.f;
        #pragma unroll
        for (int i = 0; i < Tt; ++i) tot += red[i];
        g_partial[bB] = (logCb + __logf(tot)) - goldB;
        __threadfence();
        unsigned int c = atomicAdd(&g_count, 1u);
        is_last = (c == (unsigned)gridDim.x - 1);
    }
    __syncthreads();

    // ---- last block: deterministic fixed-order reduction over batches ----
    if (is_last) {
        __threadfence();
        float sum = 0.f;
        #pragma unroll
        for (int k = 0; k < Bb / Tt; ++k) {
            float v;
            asm volatile("ld.global.cg.f32 %0, [%1];" : "=f"(v)
                         : "l"(&g_partial[to + k * Tt]));
            sum += v;
        }
        red[to] = sum;
        __syncthreads();
        if (to == 0) {
            float tot = 0.f;
            #pragma unroll
            for (int i = 0; i < Tt; ++i) tot += red[i];
            out[0] = tot;
            g_count = 0;   // reset for next (graph-replayed) launch
        }
    }
}

extern "C" void kernel_launch(void* const* d_in, const int* in_sizes, int n_in,
                              void* d_out, int out_size)
{
    (void)in_sizes; (void)n_in; (void)out_size;
    const float*         feats = (const float*)d_in[0];
    const unsigned char* mask  = (const unsigned char*)d_in[1];
    const int*           tags  = (const int*)d_in[2];
    const float*         trans = (const float*)d_in[3];

    crf_kernel<<<NBLK, Tt>>>(feats, mask, tags, trans, (float*)d_out);
}

// round 7
// speedup vs baseline: 2.3175x; 2.3175x over previous
#include <cuda_runtime.h>

// CRF NLL, exp-domain forward scan, f32x2 FMAs, 8-deep feats prefetch.
// R3 topology (512 blocks x 64 threads, 2 warps, one chain per block) +
// split-phase named barrier (arrive ... shadow work ... sync) + 8 accumulators.
// q_s[to] = (sum_from q_{s-1}[from] * E[from,to]) * exp(f_s[to]) / q_{s-1}[0]
// C_s = C_{s-1} + log(q_{s-1}[0]);  part_s = log(q_s) + C_s.

constexpr int Bb = 512;
constexpr int Ss = 512;
constexpr int Tt = 64;
constexpr int START = Tt - 2;
constexpr int STOP  = Tt - 1;
constexpr int PD    = 8;     // feats prefetch depth (steps)

__device__ float g_partial[Bb];
__device__ unsigned int g_count = 0;

typedef unsigned long long u64;

static __device__ __forceinline__ u64 fma2(u64 a, u64 b, u64 c) {
    u64 d;
    asm("fma.rn.f32x2 %0, %1, %2, %3;" : "=l"(d) : "l"(a), "l"(b), "l"(c));
    return d;
}
static __device__ __forceinline__ u64 add2(u64 a, u64 b) {
    u64 d;
    asm("add.rn.f32x2 %0, %1, %2;" : "=l"(d) : "l"(a), "l"(b));
    return d;
}
static __device__ __forceinline__ u64 pack2(float lo, float hi) {
    u64 d;
    asm("mov.b64 %0, {%1, %2};" : "=l"(d) : "f"(lo), "f"(hi));
    return d;
}
static __device__ __forceinline__ void unpack2(u64 v, float& lo, float& hi) {
    asm("mov.b64 {%0, %1}, %2;" : "=f"(lo), "=f"(hi) : "l"(v));
}
static __device__ __forceinline__ float rcp_approx(float x) {
    float r;
    asm("rcp.approx.f32 %0, %1;" : "=f"(r) : "f"(x));
    return r;
}
// Split-phase CTA barrier on named barrier 1.
// 64 threads, count 128: each thread arrives twice per phase (arrive + sync).
static __device__ __forceinline__ void bar1_arrive() {
    asm volatile("bar.arrive 1, 128;" ::: "memory");
}
static __device__ __forceinline__ void bar1_sync() {
    asm volatile("bar.sync 1, 128;" ::: "memory");
}

__global__ __launch_bounds__(Tt) void crf_kernel(
    const float* __restrict__ feats,
    const unsigned char* __restrict__ mask8,
    const int* __restrict__ tags,
    const float* __restrict__ trans,
    float* __restrict__ out)
{
    const int b  = blockIdx.x;
    const int to = threadIdx.x;   // 0..63

    __shared__ ulonglong2 qbuf[2][16];   // q (exp domain), double-buffered
    __shared__ float red[Tt];
    __shared__ int   ired[Tt];
    __shared__ int   shL;
    __shared__ bool  is_last;

    // ---- mask layout probe (uint8 vs int32) + sequence length ----
    const int* mask32 = reinterpret_cast<const int*>(mask8);
    const bool is32 = (mask8[0] == 1 && mask8[1] == 0 && mask8[2] == 0 && mask8[3] == 0);

    int cnt = 0;
    #pragma unroll
    for (int k = 0; k < Ss / Tt; ++k) {
        int s  = to + k * Tt;
        int mv = is32 ? mask32[b * Ss + s] : (int)mask8[b * Ss + s];
        cnt += (mv != 0);
    }
    ired[to] = cnt;
    __syncthreads();
    if (to == 0) {
        int L = 0;
        #pragma unroll
        for (int i = 0; i < Tt; ++i) L += ired[i];
        shL = L;
    }
    __syncthreads();
    const int L = shL;   // >= S/2 = 256

    const float* fb = feats + (size_t)b * Ss * Tt;
    const int*   tg = tags + b * Ss;

    // ---- gold path score ----
    float gsum = 0.f;
    for (int s = to; s < L; s += Tt) {
        int t1 = tg[s];
        int t0 = (s == 0) ? START : tg[s - 1];
        gsum += fb[s * Tt + t1] + trans[t0 * Tt + t1];
    }
    red[to] = gsum;
    __syncthreads();
    float gold = 0.f;
    if (to == 0) {
        #pragma unroll
        for (int i = 0; i < Tt; ++i) gold += red[i];
        gold += trans[tg[L - 1] * Tt + STOP];
    }
    __syncthreads();

    // ---- E pairs: E2[k] = (exp(trans[2k][to]), exp(trans[2k+1][to])) ----
    u64 E2[Tt / 2];
    #pragma unroll
    for (int k = 0; k < Tt / 2; ++k) {
        E2[k] = pack2(__expf(trans[(2 * k) * Tt + to]),
                      __expf(trans[(2 * k + 1) * Tt + to]));
    }

    // ---- init: part_0 = f_0 + trans[START,:]; q_0 = exp(part_0 - part_0[0]) ----
    const float part0 = fb[to] + trans[START * Tt + to];
    const float c0    = fb[0]  + trans[START * Tt];      // broadcast loads
    float logC = c0;
    reinterpret_cast<float*>(qbuf[0])[to] = __expf(part0 - c0);
    bar1_arrive();                       // open phase for step 1

    // ---- feats pipeline ----
    float fp[PD];
    #pragma unroll
    for (int r = 0; r < PD; ++r) fp[r] = fb[(1 + r) * Tt + to];   // steps 1..8

    float cur = 0.f;

    // ---- one scan step. Starts with bar.sync (q[s-1] visible), ends with
    //      STS + bar.arrive; caller places shadow work after the call. ----
    auto step = [&](int s, float f) -> float {
        bar1_sync();
        const ulonglong2* qp = qbuf[(s - 1) & 1];

        ulonglong2 w = qp[0];
        float q0, q1d;
        unpack2(w.x, q0, q1d);
        const float sc = __expf(f) * rcp_approx(q0);   // off critical path

        u64 a0 = fma2(w.x, E2[0], 0ull);
        u64 a1 = fma2(w.y, E2[1], 0ull);
        w = qp[1];
        u64 a2 = fma2(w.x, E2[2], 0ull);
        u64 a3 = fma2(w.y, E2[3], 0ull);
        w = qp[2];
        u64 a4 = fma2(w.x, E2[4], 0ull);
        u64 a5 = fma2(w.y, E2[5], 0ull);
        w = qp[3];
        u64 a6 = fma2(w.x, E2[6], 0ull);
        u64 a7 = fma2(w.y, E2[7], 0ull);
        #pragma unroll
        for (int j = 4; j < 16; j += 4) {
            w = qp[j];
            a0 = fma2(w.x, E2[2 * j],     a0);
            a1 = fma2(w.y, E2[2 * j + 1], a1);
            w = qp[j + 1];
            a2 = fma2(w.x, E2[2 * j + 2], a2);
            a3 = fma2(w.y, E2[2 * j + 3], a3);
            w = qp[j + 2];
            a4 = fma2(w.x, E2[2 * j + 4], a4);
            a5 = fma2(w.y, E2[2 * j + 5], a5);
            w = qp[j + 3];
            a6 = fma2(w.x, E2[2 * j + 6], a6);
            a7 = fma2(w.y, E2[2 * j + 7], a7);
        }
        const u64 t = add2(add2(add2(a0, a1), add2(a2, a3)),
                           add2(add2(a4, a5), add2(a6, a7)));
        float lo, hi;
        unpack2(t, lo, hi);
        const float raw = (lo + hi) * sc;

        reinterpret_cast<float*>(qbuf[s & 1])[to] = raw;
        cur = raw;
        bar1_arrive();
        return q0;      // shadow region consumes this (logC)
    };

    // ---- forward scan, unrolled x8; prefetch + logC live in the shadow ----
    int s = 1;
    for (; s + (PD - 1) < L; ) {
        #pragma unroll
        for (int r = 0; r < PD; ++r) {
            const float f = fp[r];
            const float q0 = step(s, f);
            // -------- shadow region (between arrive and next sync) --------
            if (s + PD < L) fp[r] = fb[(s + PD) * Tt + to];
            logC += __logf(q0);
            ++s;
        }
    }
    for (; s < L; ++s) {
        const float q0 = step(s, fp[(s - 1) & (PD - 1)]);
        logC += __logf(q0);
    }
    bar1_sync();   // close the last phase

    // ---- final transition to STOP ----
    red[to] = cur * __expf(trans[to * Tt + STOP]);
    __syncthreads();
    if (to == 0) {
        float tot = 0.f;
        #pragma unroll
        for (int i = 0; i < Tt; ++i) tot += red[i];
        const float fwd = logC + __logf(tot);
        g_partial[b] = fwd - gold;
        __threadfence();
        unsigned int c = atomicAdd(&g_count, 1u);
        is_last = (c == (unsigned)gridDim.x - 1);
    }
    __syncthreads();

    // ---- last block: deterministic fixed-order reduction over batches ----
    if (is_last) {
        __threadfence();
        float sum = 0.f;
        #pragma unroll
        for (int k = 0; k < Bb / Tt; ++k) {
            float v;
            asm volatile("ld.global.cg.f32 %0, [%1];" : "=f"(v)
                         : "l"(&g_partial[to + k * Tt]));
            sum += v;
        }
        red[to] = sum;
        __syncthreads();
        if (to == 0) {
            float tot = 0.f;
            #pragma unroll
            for (int i = 0; i < Tt; ++i) tot += red[i];
            out[0] = tot;
            g_count = 0;   // reset for next (graph-replayed) launch
        }
    }
}

extern "C" void kernel_launch(void* const* d_in, const int* in_sizes, int n_in,
                              void* d_out, int out_size)
{
    (void)in_sizes; (void)n_in; (void)out_size;
    const float*         feats = (const float*)d_in[0];
    const unsigned char* mask  = (const unsigned char*)d_in[1];
    const int*           tags  = (const int*)d_in[2];
    const float*         trans = (const float*)d_in[3];

    crf_kernel<<<Bb, Tt>>>(feats, mask, tags, trans, (float*)d_out);
}